// round 3
// baseline (speedup 1.0000x reference)
#include <cuda_runtime.h>

#define NCH 30          // 5*B + C channels per cell
#define CPB 128         // cells per block (one thread per cell)
#define SCELL 49        // S*S

__device__ float g_partials[8192];
__device__ unsigned int g_count;   // zero at module load; reset by last block

__global__ void __launch_bounds__(CPB) yolo_loss_kernel(
    const float* __restrict__ pred, const float* __restrict__ target,
    float invN, float* __restrict__ out)
{
    __shared__ float sp[CPB * NCH];   // 15360 B
    __shared__ float st[CPB * NCH];   // 15360 B
    __shared__ float warpsum[CPB / 32];
    __shared__ unsigned int s_rank;

    const int tid = threadIdx.x;
    const size_t base = (size_t)blockIdx.x * (CPB * NCH);

    // ---- coalesced staging: contiguous float4 loads ----
    const float4* p4 = (const float4*)(pred + base);
    const float4* t4 = (const float4*)(target + base);
    float4* sp4 = (float4*)sp;
    float4* st4 = (float4*)st;
    const int NV4 = CPB * NCH / 4;    // 960
    #pragma unroll
    for (int i = 0; i < (NV4 + CPB - 1) / CPB; ++i) {
        int idx = tid + i * CPB;
        if (idx < NV4) { sp4[idx] = p4[idx]; st4[idx] = t4[idx]; }
    }
    __syncthreads();

    // ---- per-cell loss ----
    const float* P = sp + tid * NCH;
    const float* T = st + tid * NCH;
    const int cell = blockIdx.x * CPB + tid;
    const int c49 = cell % SCELL;
    const float gy = (float)(c49 / 7);   // axis-1 (row) index
    const float gx = (float)(c49 % 7);   // axis-2 (col) index
    const float STEP = 1.0f / 7.0f;

    const float mask = (T[9] > 0.0f) ? 1.0f : 0.0f;

    float iou[2];
    #pragma unroll
    for (int b = 0; b < 2; ++b) {
        const float* pb = P + 5 * b;
        const float* tb = T + 5 * b;
        // convert: x0/y0 use UNclipped w/h; then all 4 outputs clipped at 0
        float pw = fmaxf(pb[2], 0.0f), ph = fmaxf(pb[3], 0.0f);
        float px = fmaxf((pb[0] + gx) * STEP - pb[2] * 0.5f, 0.0f);
        float py = fmaxf((pb[1] + gy) * STEP - pb[3] * 0.5f, 0.0f);
        float tw = fmaxf(tb[2], 0.0f), th = fmaxf(tb[3], 0.0f);
        float tx = fmaxf((tb[0] + gx) * STEP - tb[2] * 0.5f, 0.0f);
        float ty = fmaxf((tb[1] + gy) * STEP - tb[3] * 0.5f, 0.0f);
        float iw = fmaxf(pw + tw - (fmaxf(px + pw, tx + tw) - fminf(px, tx)), 0.0f);
        float ih = fmaxf(ph + th - (fmaxf(py + ph, ty + th) - fminf(py, ty)), 0.0f);
        float inter = iw * ih;
        float uni = pw * ph + tw * th - inter;
        iou[b] = inter / (uni + 1e-10f);
    }
    // jnp.argmax: first max → box 1 only if strictly greater
    const int resp = (iou[1] > iou[0]) ? 1 : 0;

    float loss = 0.0f;
    #pragma unroll
    for (int b = 0; b < 2; ++b) {
        const float ob = (b == resp) ? mask : 0.0f;
        const float* pb = P + 5 * b;
        const float* tb = T + 5 * b;
        float d0 = pb[0] - tb[0], d1 = pb[1] - tb[1];
        float d2 = pb[2] - tb[2], d3 = pb[3] - tb[3];
        loss += 5.0f * ob * (d0 * d0 + d1 * d1 + d2 * d2 + d3 * d3);
        float c = pb[4];
        float dc = c - iou[b];
        loss += ob * dc * dc + 0.5f * (1.0f - ob) * c * c;
    }
    float cls = 0.0f;
    #pragma unroll
    for (int k = 10; k < 30; ++k) {
        float d = P[k] - T[k];
        cls += d * d;
    }
    loss += mask * cls;

    // ---- deterministic block reduction ----
    #pragma unroll
    for (int o = 16; o; o >>= 1)
        loss += __shfl_down_sync(0xffffffffu, loss, o);
    if ((tid & 31) == 0) warpsum[tid >> 5] = loss;
    __syncthreads();
    if (tid == 0) {
        float s = 0.0f;
        #pragma unroll
        for (int w = 0; w < CPB / 32; ++w) s += warpsum[w];
        g_partials[blockIdx.x] = s;
        __threadfence();
        s_rank = atomicAdd(&g_count, 1u);
    }
    __syncthreads();

    // ---- last block folds all partials (fixed order -> deterministic) ----
    if (s_rank == gridDim.x - 1) {
        __threadfence();
        const int nb = gridDim.x;          // multiple of 4 (6272)
        const int nv = nb / 4;
        const float4* g4 = (const float4*)g_partials;
        float s = 0.0f;
        for (int i = tid; i < nv; i += CPB) {
            float4 v = g4[i];
            s += (v.x + v.y) + (v.z + v.w);
        }
        #pragma unroll
        for (int o = 16; o; o >>= 1)
            s += __shfl_down_sync(0xffffffffu, s, o);
        if ((tid & 31) == 0) warpsum[tid >> 5] = s;
        __syncthreads();
        if (tid == 0) {
            float tot = 0.0f;
            #pragma unroll
            for (int w = 0; w < CPB / 32; ++w) tot += warpsum[w];
            out[0] = tot * invN;
            g_count = 0;                   // reset for graph replay
        }
    }
}

extern "C" void kernel_launch(void* const* d_in, const int* in_sizes, int n_in,
                              void* d_out, int out_size)
{
    const float* pred   = (const float*)d_in[0];
    const float* target = (const float*)d_in[1];
    const int total  = in_sizes[0];          // N * 49 * 30
    const int ncells = total / NCH;          // N * 49 = 802816
    const int nblocks = ncells / CPB;        // 6272 (exact)
    const float invN = 1.0f / (float)(ncells / SCELL);

    yolo_loss_kernel<<<nblocks, CPB>>>(pred, target, invN, (float*)d_out);
}

// round 4
// speedup vs baseline: 1.0985x; 1.0985x over previous
#include <cuda_runtime.h>
#include <cstdint>

#define NCH   30            // channels per cell
#define TILE  64            // cells per pipeline stage
#define THR   128           // threads per CTA (staging); 64 compute
#define SCELL 49
#define STAGE_F (TILE * NCH * 2)   // floats per stage (pred+target) = 3840
#define GRID  444           // ~3 CTAs/SM, persistent

__device__ float g_partials[1024];
__device__ unsigned int g_count;    // zeroed at load; reset by last CTA

__device__ __forceinline__ void cp16(uint32_t saddr, const void* gptr) {
    asm volatile("cp.async.cg.shared.global [%0], [%1], 16;"
                 :: "r"(saddr), "l"(gptr) : "memory");
}
__device__ __forceinline__ void cp_commit() {
    asm volatile("cp.async.commit_group;" ::: "memory");
}

// stage a full tile (960 float4: 480 pred + 480 target) cooperatively
__device__ __forceinline__ void issue_tile(uint32_t sbase, const float4* p4,
                                           const float4* t4, int tile, int tid) {
    const float4* gp = p4 + (size_t)tile * 480;
    const float4* gt = t4 + (size_t)tile * 480;
    // i in [0,960): first 480 -> pred half, next 480 -> target half
    #pragma unroll
    for (int k = 0; k < 8; ++k) {
        int i = tid + k * THR;
        if (i < 960) {
            if (i < 480) cp16(sbase + i * 16, gp + i);
            else         cp16(sbase + 480 * 16 + (i - 480) * 16, gt + (i - 480));
        }
    }
    cp_commit();
}

__global__ void __launch_bounds__(THR) yolo_loss_pipe(
    const float* __restrict__ pred, const float* __restrict__ target,
    int ntiles, float invN, float* __restrict__ out)
{
    __shared__ float buf[2 * STAGE_F];        // 30720 B
    __shared__ float warpsum[2];
    __shared__ unsigned int s_rank;

    const int tid = threadIdx.x;
    const uint32_t sm0 = (uint32_t)__cvta_generic_to_shared(buf);
    const float4* p4 = (const float4*)pred;
    const float4* t4 = (const float4*)target;

    const int bx = blockIdx.x;
    const int my_n = (bx < ntiles) ? (ntiles - bx + GRID - 1) / GRID : 0;
    float acc = 0.0f;                          // meaningful in tid 0 only
    const float STEP = 1.0f / 7.0f;

    if (my_n > 0)
        issue_tile(sm0, p4, t4, bx, tid);      // prologue -> stage 0

    for (int it = 0; it < my_n; ++it) {
        const int tile = bx + it * GRID;
        const bool has_next = (it + 1 < my_n);
        if (has_next) {
            issue_tile(sm0 + ((it + 1) & 1) * (STAGE_F * 4), p4, t4,
                       tile + GRID, tid);
            asm volatile("cp.async.wait_group 1;" ::: "memory");
        } else {
            asm volatile("cp.async.wait_group 0;" ::: "memory");
        }
        __syncthreads();

        float loss = 0.0f;
        if (tid < TILE) {
            const float* S = buf + (it & 1) * STAGE_F;
            const float* P = S + tid * NCH;
            const float* T = S + TILE * NCH + tid * NCH;
            const int cell = tile * TILE + tid;
            const int c49 = cell % SCELL;
            const float gy = (float)(c49 / 7);
            const float gx = (float)(c49 % 7);

            const float mask = (T[9] > 0.0f) ? 1.0f : 0.0f;

            float iou[2];
            #pragma unroll
            for (int b = 0; b < 2; ++b) {
                const float* pb = P + 5 * b;
                const float* tb = T + 5 * b;
                float pw = fmaxf(pb[2], 0.0f), ph = fmaxf(pb[3], 0.0f);
                float px = fmaxf((pb[0] + gx) * STEP - pb[2] * 0.5f, 0.0f);
                float py = fmaxf((pb[1] + gy) * STEP - pb[3] * 0.5f, 0.0f);
                float tw = fmaxf(tb[2], 0.0f), th = fmaxf(tb[3], 0.0f);
                float tx = fmaxf((tb[0] + gx) * STEP - tb[2] * 0.5f, 0.0f);
                float ty = fmaxf((tb[1] + gy) * STEP - tb[3] * 0.5f, 0.0f);
                float iw = fmaxf(pw + tw - (fmaxf(px + pw, tx + tw) - fminf(px, tx)), 0.0f);
                float ih = fmaxf(ph + th - (fmaxf(py + ph, ty + th) - fminf(py, ty)), 0.0f);
                float inter = iw * ih;
                float uni = pw * ph + tw * th - inter;
                iou[b] = inter / (uni + 1e-10f);
            }
            const int resp = (iou[1] > iou[0]) ? 1 : 0;

            #pragma unroll
            for (int b = 0; b < 2; ++b) {
                const float ob = (b == resp) ? mask : 0.0f;
                const float* pb = P + 5 * b;
                const float* tb = T + 5 * b;
                float d0 = pb[0] - tb[0], d1 = pb[1] - tb[1];
                float d2 = pb[2] - tb[2], d3 = pb[3] - tb[3];
                loss += 5.0f * ob * (d0 * d0 + d1 * d1 + d2 * d2 + d3 * d3);
                float c = pb[4];
                float dc = c - iou[b];
                loss += ob * dc * dc + 0.5f * (1.0f - ob) * c * c;
            }
            float cls = 0.0f;
            #pragma unroll
            for (int k = 10; k < 30; ++k) {
                float d = P[k] - T[k];
                cls += d * d;
            }
            loss += mask * cls;

            #pragma unroll
            for (int o = 16; o; o >>= 1)
                loss += __shfl_down_sync(0xffffffffu, loss, o);
            if ((tid & 31) == 0) warpsum[tid >> 5] = loss;
        }
        __syncthreads();
        if (tid == 0) acc += warpsum[0] + warpsum[1];
    }

    // ---- publish CTA partial, fence-free (L2-direct + acq_rel atomic) ----
    if (tid == 0) {
        __stcg(&g_partials[bx], acc);
        unsigned int rank;
        asm volatile("atom.acq_rel.gpu.global.add.u32 %0, [%1], %2;"
                     : "=r"(rank) : "l"(&g_count), "r"(1u) : "memory");
        s_rank = rank;
    }
    __syncthreads();

    // ---- last CTA folds all partials in fixed order ----
    if (s_rank == GRID - 1) {
        float s = 0.0f;
        for (int i = tid; i < GRID; i += THR)
            s += __ldcg(&g_partials[i]);
        #pragma unroll
        for (int o = 16; o; o >>= 1)
            s += __shfl_down_sync(0xffffffffu, s, o);
        __shared__ float fin[THR / 32];
        if ((tid & 31) == 0) fin[tid >> 5] = s;
        __syncthreads();
        if (tid == 0) {
            float tot = 0.0f;
            #pragma unroll
            for (int w = 0; w < THR / 32; ++w) tot += fin[w];
            out[0] = tot * invN;
            g_count = 0;                        // reset for graph replay
        }
    }
}

extern "C" void kernel_launch(void* const* d_in, const int* in_sizes, int n_in,
                              void* d_out, int out_size)
{
    const float* pred   = (const float*)d_in[0];
    const float* target = (const float*)d_in[1];
    const int total  = in_sizes[0];           // N*49*30
    const int ncells = total / NCH;           // 802816
    const int ntiles = ncells / TILE;         // 12544 (exact)
    const float invN = 1.0f / (float)(ncells / SCELL);

    yolo_loss_pipe<<<GRID, THR>>>(pred, target, ntiles, invN, (float*)d_out);
}

// round 5
// speedup vs baseline: 1.1644x; 1.0599x over previous
#include <cuda_runtime.h>
#include <cstdint>

#define NCH   30            // channels per cell
#define TILE  64            // cells per pipeline stage
#define THR   128           // threads per CTA
#define SCELL 49
#define STAGE_F (TILE * NCH * 2)   // floats per stage (pred+target) = 3840
#define GRID  1036          // 7 CTAs/SM on 148 SMs (smem-limited max)

__device__ float g_partials[2048];
__device__ unsigned int g_count;    // zeroed at load; reset by last CTA

__device__ __forceinline__ void cp16(uint32_t saddr, const void* gptr) {
    asm volatile("cp.async.cg.shared.global [%0], [%1], 16;"
                 :: "r"(saddr), "l"(gptr) : "memory");
}

// stage a full tile (960 float4: 480 pred + 480 target) cooperatively
__device__ __forceinline__ void issue_tile(uint32_t sbase, const float4* p4,
                                           const float4* t4, int tile, int tid) {
    const float4* gp = p4 + (size_t)tile * 480;
    const float4* gt = t4 + (size_t)tile * 480;
    #pragma unroll
    for (int k = 0; k < 8; ++k) {
        int i = tid + k * THR;
        if (i < 960) {
            if (i < 480) cp16(sbase + i * 16, gp + i);
            else         cp16(sbase + 480 * 16 + (i - 480) * 16, gt + (i - 480));
        }
    }
    asm volatile("cp.async.commit_group;" ::: "memory");
}

__global__ void __launch_bounds__(THR) yolo_loss_pipe(
    const float* __restrict__ pred, const float* __restrict__ target,
    int ntiles, float invN, float* __restrict__ out)
{
    __shared__ float buf[2 * STAGE_F];        // 30720 B -> 7 CTAs/SM
    __shared__ float warpsum[4];
    __shared__ unsigned int s_rank;

    const int tid = threadIdx.x;
    const uint32_t sm0 = (uint32_t)__cvta_generic_to_shared(buf);
    const float4* p4 = (const float4*)pred;
    const float4* t4 = (const float4*)target;

    const int bx = blockIdx.x;
    const int my_n = (bx < ntiles) ? (ntiles - bx + GRID - 1) / GRID : 0;
    float acc = 0.0f;                          // meaningful in tid 0 only
    const float STEP = 1.0f / 7.0f;

    if (my_n > 0)
        issue_tile(sm0, p4, t4, bx, tid);      // prologue -> stage 0

    for (int it = 0; it < my_n; ++it) {
        const int tile = bx + it * GRID;
        const bool has_next = (it + 1 < my_n);
        if (has_next) {
            issue_tile(sm0 + ((it + 1) & 1) * (STAGE_F * 4), p4, t4,
                       tile + GRID, tid);
            asm volatile("cp.async.wait_group 1;" ::: "memory");
        } else {
            asm volatile("cp.async.wait_group 0;" ::: "memory");
        }
        __syncthreads();

        const float* S = buf + (it & 1) * STAGE_F;
        float loss = 0.0f;

        if (tid < TILE) {
            // ---- warps 0-1: box/conf/IoU losses for cell tid ----
            const float* P = S + tid * NCH;
            const float* T = S + TILE * NCH + tid * NCH;
            const int cell = tile * TILE + tid;
            const int c49 = cell % SCELL;
            const float gy = (float)(c49 / 7);
            const float gx = (float)(c49 % 7);
            const float mask = (T[9] > 0.0f) ? 1.0f : 0.0f;

            float iou[2];
            #pragma unroll
            for (int b = 0; b < 2; ++b) {
                const float* pb = P + 5 * b;
                const float* tb = T + 5 * b;
                float pw = fmaxf(pb[2], 0.0f), ph = fmaxf(pb[3], 0.0f);
                float px = fmaxf((pb[0] + gx) * STEP - pb[2] * 0.5f, 0.0f);
                float py = fmaxf((pb[1] + gy) * STEP - pb[3] * 0.5f, 0.0f);
                float tw = fmaxf(tb[2], 0.0f), th = fmaxf(tb[3], 0.0f);
                float tx = fmaxf((tb[0] + gx) * STEP - tb[2] * 0.5f, 0.0f);
                float ty = fmaxf((tb[1] + gy) * STEP - tb[3] * 0.5f, 0.0f);
                float iw = fmaxf(pw + tw - (fmaxf(px + pw, tx + tw) - fminf(px, tx)), 0.0f);
                float ih = fmaxf(ph + th - (fmaxf(py + ph, ty + th) - fminf(py, ty)), 0.0f);
                float inter = iw * ih;
                float uni = pw * ph + tw * th - inter;
                iou[b] = inter / (uni + 1e-10f);
            }
            const int resp = (iou[1] > iou[0]) ? 1 : 0;

            #pragma unroll
            for (int b = 0; b < 2; ++b) {
                const float ob = (b == resp) ? mask : 0.0f;
                const float* pb = P + 5 * b;
                const float* tb = T + 5 * b;
                float d0 = pb[0] - tb[0], d1 = pb[1] - tb[1];
                float d2 = pb[2] - tb[2], d3 = pb[3] - tb[3];
                loss += 5.0f * ob * (d0 * d0 + d1 * d1 + d2 * d2 + d3 * d3);
                float c = pb[4];
                float dc = c - iou[b];
                loss += ob * dc * dc + 0.5f * (1.0f - ob) * c * c;
            }
        } else {
            // ---- warps 2-3: class loss for cell (tid-64) ----
            const int ct = tid - TILE;
            const float* P = S + ct * NCH;
            const float* T = S + TILE * NCH + ct * NCH;
            const float mask = (T[9] > 0.0f) ? 1.0f : 0.0f;
            float cls = 0.0f;
            #pragma unroll
            for (int k = 10; k < 30; ++k) {
                float d = P[k] - T[k];
                cls += d * d;
            }
            loss = mask * cls;
        }

        #pragma unroll
        for (int o = 16; o; o >>= 1)
            loss += __shfl_down_sync(0xffffffffu, loss, o);
        if ((tid & 31) == 0) warpsum[tid >> 5] = loss;
        __syncthreads();
        if (tid == 0)
            acc += (warpsum[0] + warpsum[1]) + (warpsum[2] + warpsum[3]);
    }

    // ---- publish CTA partial, fence-free (L2-direct + acq_rel atomic) ----
    if (tid == 0) {
        __stcg(&g_partials[bx], acc);
        unsigned int rank;
        asm volatile("atom.acq_rel.gpu.global.add.u32 %0, [%1], %2;"
                     : "=r"(rank) : "l"(&g_count), "r"(1u) : "memory");
        s_rank = rank;
    }
    __syncthreads();

    // ---- last CTA folds all partials in fixed order ----
    if (s_rank == GRID - 1) {
        float s = 0.0f;
        for (int i = tid; i < GRID; i += THR)
            s += __ldcg(&g_partials[i]);
        #pragma unroll
        for (int o = 16; o; o >>= 1)
            s += __shfl_down_sync(0xffffffffu, s, o);
        __shared__ float fin[THR / 32];
        if ((tid & 31) == 0) fin[tid >> 5] = s;
        __syncthreads();
        if (tid == 0) {
            float tot = 0.0f;
            #pragma unroll
            for (int w = 0; w < THR / 32; ++w) tot += fin[w];
            out[0] = tot * invN;
            g_count = 0;                        // reset for graph replay
        }
    }
}

extern "C" void kernel_launch(void* const* d_in, const int* in_sizes, int n_in,
                              void* d_out, int out_size)
{
    const float* pred   = (const float*)d_in[0];
    const float* target = (const float*)d_in[1];
    const int total  = in_sizes[0];           // N*49*30
    const int ncells = total / NCH;           // 802816
    const int ntiles = ncells / TILE;         // 12544 (exact)
    const float invN = 1.0f / (float)(ncells / SCELL);

    yolo_loss_pipe<<<GRID, THR>>>(pred, target, ntiles, invN, (float*)d_out);
}